// round 1
// baseline (speedup 1.0000x reference)
#include <cuda_runtime.h>
#include <cuda_bf16.h>
#include <cstdint>

// Embedding gather: out[row, :] = table[token_ids[row], :]
//   table: [50257, 768] fp32 (d_in[1])
//   ids:   [16384]  int64 OR int32 (d_in[0]) -- width auto-detected
//   out:   [16384, 768] fp32
//
// Pure HBM-bound copy: ~48 MiB write + <=48 MiB gathered read.

#define VOCAB    50257
#define D_MODEL  768
#define VEC_PER_ROW (D_MODEL / 4)   // 192 float4 per row

// Flag: 1 if ids buffer is int64, 0 if int32. Written by detect kernel,
// consumed by gather kernel (same stream => ordered under graph replay).
__device__ int g_ids_is64;

// Read the first 4096 aligned 8-byte words (32 KiB). Safe under both layouts:
//   int64 layout: buffer is 128 KiB; int32 layout: buffer is 64 KiB.
// If the data is int32-packed, a u64 word holds two tokens (t_lo + t_hi<<32);
// with 4096 samples the chance every t_hi is zero is ~(1/VOCAB)^4096 ~= 0.
// If the data is genuine int64, every word is a token < VOCAB.
__global__ void detect_ids_width(const unsigned long long* __restrict__ ids_u64) {
    __shared__ int s_bad;
    if (threadIdx.x == 0) s_bad = 0;
    __syncthreads();
    int bad = 0;
    for (int i = threadIdx.x; i < 4096; i += blockDim.x) {
        if (ids_u64[i] >= (unsigned long long)VOCAB) bad = 1;
    }
    if (bad) atomicOr(&s_bad, 1);
    __syncthreads();
    if (threadIdx.x == 0) g_ids_is64 = s_bad ? 0 : 1;
}

// One CTA per output row; 192 threads x 16 B = 3072 B = one full row.
__global__ __launch_bounds__(VEC_PER_ROW)
void embedding_gather_kernel(const void* __restrict__ ids,
                             const float4* __restrict__ table,
                             float4* __restrict__ out) {
    const int row = blockIdx.x;

    long long tok;
    if (g_ids_is64) {
        tok = ((const long long*)ids)[row];
    } else {
        tok = (long long)((const int*)ids)[row];
    }

    const float4* __restrict__ src = table + tok * (long long)VEC_PER_ROW;
    float4* __restrict__ dst = out + (long long)row * VEC_PER_ROW;

    // Uniform per-block token => src base is broadcast; both accesses are
    // fully coalesced 128-bit transactions.
    dst[threadIdx.x] = src[threadIdx.x];
}

extern "C" void kernel_launch(void* const* d_in, const int* in_sizes, int n_in,
                              void* d_out, int out_size) {
    const void*   ids   = d_in[0];
    const float4* table = (const float4*)d_in[1];
    float4*       out   = (float4*)d_out;

    const int rows = out_size / D_MODEL;   // 16384, dtype-independent

    detect_ids_width<<<1, 256>>>((const unsigned long long*)ids);
    embedding_gather_kernel<<<rows, VEC_PER_ROW>>>(ids, table, out);
}

// round 2
// speedup vs baseline: 1.4769x; 1.4769x over previous
#include <cuda_runtime.h>
#include <cuda_bf16.h>
#include <cstdint>

// Embedding gather: out[row, :] = table[token_ids[row], :]
//   table: [50257, 768] fp32 (d_in[1])
//   ids:   [16384]  int64 OR int32 (d_in[0]) -- width auto-detected
//   out:   [16384, 768] fp32
//
// Latency-bound gather -> boost MLP: 4 rows/CTA, 4 independent LDG.128 per
// thread, streaming stores so the write-only output doesn't evict table L2.

#define VOCAB       50257
#define D_MODEL     768
#define VEC_PER_ROW (D_MODEL / 4)   // 192 float4 per row
#define N_ROWS      16384
#define ROWS_PER_CTA 4

// Hot int32 token array (64 KiB) produced by the convert kernel.
__device__ int g_tokens[N_ROWS];

// Detect id width from a shared sample, then convert this block's slice to
// int32. All blocks read the SAME first 512 u64 words (4 KiB, L2-broadcast)
// so every block reaches the same verdict deterministically.
//   int64 layout: all u64 words are tokens < VOCAB.
//   int32 layout: words pack two tokens; P(all 512 high halves < VOCAB as
//   u64... i.e. look like valid tokens) ~ (1/VOCAB)^512 ~= 0.
// Sample is in-bounds under both layouts (int32 buffer = 8192 u64 words).
__global__ void convert_ids_kernel(const unsigned long long* __restrict__ ids_u64) {
    bool is64 = true;
    #pragma unroll 4
    for (int i = threadIdx.x & 127; i < 512; i += 128) {
        if (ids_u64[i] >= (unsigned long long)VOCAB) is64 = false;
    }
    // warp-uniform verdict
    is64 = __all_sync(0xFFFFFFFFu, is64);

    const int idx = blockIdx.x * blockDim.x + threadIdx.x;
    if (idx < N_ROWS) {
        int tok;
        if (is64) tok = (int)((const long long*)ids_u64)[idx];
        else      tok = ((const int*)ids_u64)[idx];
        g_tokens[idx] = tok;
    }
}

// 4 rows per CTA, 192 threads; each thread moves one float4 from each row.
// 4 independent gathered LDG.128 in flight per thread (MLP=4), then 4
// streaming STG.128.
__global__ __launch_bounds__(VEC_PER_ROW)
void embedding_gather_kernel(const float4* __restrict__ table,
                             float4* __restrict__ out) {
    const int row0 = blockIdx.x * ROWS_PER_CTA;
    const int t = threadIdx.x;

    int tok[ROWS_PER_CTA];
    #pragma unroll
    for (int j = 0; j < ROWS_PER_CTA; j++)
        tok[j] = g_tokens[row0 + j];          // block-uniform, L2-hot

    float4 v[ROWS_PER_CTA];
    #pragma unroll
    for (int j = 0; j < ROWS_PER_CTA; j++)
        v[j] = __ldg(table + (long long)tok[j] * VEC_PER_ROW + t);

    float4* dst = out + (long long)row0 * VEC_PER_ROW + t;
    #pragma unroll
    for (int j = 0; j < ROWS_PER_CTA; j++)
        __stcs(dst + (long long)j * VEC_PER_ROW, v[j]);
}

extern "C" void kernel_launch(void* const* d_in, const int* in_sizes, int n_in,
                              void* d_out, int out_size) {
    const void*   ids   = d_in[0];
    const float4* table = (const float4*)d_in[1];
    float4*       out   = (float4*)d_out;

    convert_ids_kernel<<<N_ROWS / 256, 256>>>((const unsigned long long*)ids);
    embedding_gather_kernel<<<N_ROWS / ROWS_PER_CTA, VEC_PER_ROW>>>(table, out);
}